// round 4
// baseline (speedup 1.0000x reference)
#include <cuda_runtime.h>
#include <cstdint>
#include <cstddef>

#define B_SZ 8
#define T_SZ 1024
#define D_SZ 256
#define H_SZ 512
#define M_SZ 1024
#define R_SZ 4

// ---------------------------------------------------------------------------
// Scratch (static device globals -- no runtime allocation allowed)
// ---------------------------------------------------------------------------
__device__ float g_xz[(size_t)B_SZ * T_SZ * 4 * H_SZ];   // 64 MB  [b*T+t][4H]
__device__ float g_h [(size_t)B_SZ * T_SZ * H_SZ];       // 16 MB  [b*T+t][H]
__device__ float g_rk[(size_t)R_SZ * B_SZ * T_SZ * M_SZ];// 128 MB [r][b*T+t][M]
__device__ float g_wk[(size_t)B_SZ * T_SZ * M_SZ];       // 32 MB
__device__ float g_eb[(size_t)B_SZ * T_SZ * M_SZ];       // 32 MB erase logits
__device__ float g_ab[(size_t)B_SZ * T_SZ * M_SZ];       // 32 MB add logits
__device__ float g_sim [R_SZ * B_SZ * T_SZ];
__device__ float g_simw[B_SZ * T_SZ];
__device__ float g_ww  [B_SZ * T_SZ];
__device__ float g_invn[M_SZ];
__device__ float g_colsum[M_SZ];
__device__ unsigned g_flags[128];   // per-CTA step counters (barrier)

// ---------------------------------------------------------------------------
// Block-wide reductions (blockDim.x == 256)
// ---------------------------------------------------------------------------
__device__ __forceinline__ float blockReduceSum(float v) {
    __shared__ float sh[8];
    int lane = threadIdx.x & 31, w = threadIdx.x >> 5;
#pragma unroll
    for (int o = 16; o; o >>= 1) v += __shfl_xor_sync(0xffffffffu, v, o);
    if (lane == 0) sh[w] = v;
    __syncthreads();
    if (w == 0) {
        float x = (lane < 8) ? sh[lane] : 0.f;
#pragma unroll
        for (int o = 4; o; o >>= 1) x += __shfl_xor_sync(0xffffffffu, x, o);
        if (lane == 0) sh[0] = x;
    }
    __syncthreads();
    float r = sh[0];
    __syncthreads();
    return r;
}

__device__ __forceinline__ float blockReduceMax(float v) {
    __shared__ float sh[8];
    int lane = threadIdx.x & 31, w = threadIdx.x >> 5;
#pragma unroll
    for (int o = 16; o; o >>= 1) v = fmaxf(v, __shfl_xor_sync(0xffffffffu, v, o));
    if (lane == 0) sh[w] = v;
    __syncthreads();
    if (w == 0) {
        float x = (lane < 8) ? sh[lane] : -3.402823466e38f;
#pragma unroll
        for (int o = 4; o; o >>= 1) x = fmaxf(x, __shfl_xor_sync(0xffffffffu, x, o));
        if (lane == 0) sh[0] = x;
    }
    __syncthreads();
    float r = sh[0];
    __syncthreads();
    return r;
}

__device__ __forceinline__ float sigmoidf_(float x) {
    return 1.f / (1.f + __expf(-x));
}

// ---------------------------------------------------------------------------
// Generic SGEMM: C = A[M,K] @ B[K,N] + bias[N]   (128x128 tile, 256 threads)
// ---------------------------------------------------------------------------
__global__ void __launch_bounds__(256) sgemm_kernel(
    const float* __restrict__ A, const float* __restrict__ B,
    const float* __restrict__ bias, float* __restrict__ C,
    int M, int N, int K, long zB, long zBias, long zC)
{
    const int n0 = blockIdx.x * 128;
    const int m0 = blockIdx.y * 128;
    B    += (size_t)blockIdx.z * (size_t)zB;
    bias += (size_t)blockIdx.z * (size_t)zBias;
    C    += (size_t)blockIdx.z * (size_t)zC;

    __shared__ float As[8][128];
    __shared__ float Bs[8][128];

    const int tid  = threadIdx.x;
    const int arow = tid >> 1, ak = (tid & 1) * 4;
    const int bk   = tid >> 5, bc = (tid & 31) * 4;
    const int tx   = tid & 15, ty = tid >> 4;

    const float* Ap = A + (size_t)(m0 + arow) * K + ak;
    const float* Bp = B + (size_t)bk * N + n0 + bc;

    float4 aR = *(const float4*)Ap;
    float4 bR = *(const float4*)Bp;

    float acc[8][8];
#pragma unroll
    for (int i = 0; i < 8; i++)
#pragma unroll
        for (int j = 0; j < 8; j++) acc[i][j] = 0.f;

    const int KT = K >> 3;
    for (int kt = 0; kt < KT; kt++) {
        As[ak + 0][arow] = aR.x;
        As[ak + 1][arow] = aR.y;
        As[ak + 2][arow] = aR.z;
        As[ak + 3][arow] = aR.w;
        *(float4*)&Bs[bk][bc] = bR;
        __syncthreads();
        if (kt + 1 < KT) {
            aR = *(const float4*)(Ap + (kt + 1) * 8);
            bR = *(const float4*)(Bp + (size_t)(kt + 1) * 8 * N);
        }
#pragma unroll
        for (int kk = 0; kk < 8; kk++) {
            float4 a0 = *(const float4*)&As[kk][ty * 4];
            float4 a1 = *(const float4*)&As[kk][64 + ty * 4];
            float4 b0 = *(const float4*)&Bs[kk][tx * 4];
            float4 b1 = *(const float4*)&Bs[kk][64 + tx * 4];
            float ar[8] = {a0.x, a0.y, a0.z, a0.w, a1.x, a1.y, a1.z, a1.w};
            float br[8] = {b0.x, b0.y, b0.z, b0.w, b1.x, b1.y, b1.z, b1.w};
#pragma unroll
            for (int i = 0; i < 8; i++)
#pragma unroll
                for (int j = 0; j < 8; j++) acc[i][j] += ar[i] * br[j];
        }
        __syncthreads();
    }

    float4 bias0 = *(const float4*)&bias[n0 + tx * 4];
    float4 bias1 = *(const float4*)&bias[n0 + 64 + tx * 4];
    float bb[8] = {bias0.x, bias0.y, bias0.z, bias0.w,
                   bias1.x, bias1.y, bias1.z, bias1.w};
#pragma unroll
    for (int i = 0; i < 8; i++) {
        int row = m0 + ((i < 4) ? (ty * 4 + i) : (64 + ty * 4 + (i - 4)));
        float4 o0 = make_float4(acc[i][0] + bb[0], acc[i][1] + bb[1],
                                acc[i][2] + bb[2], acc[i][3] + bb[3]);
        float4 o1 = make_float4(acc[i][4] + bb[4], acc[i][5] + bb[5],
                                acc[i][6] + bb[6], acc[i][7] + bb[7]);
        *(float4*)&C[(size_t)row * N + n0 + tx * 4]      = o0;
        *(float4*)&C[(size_t)row * N + n0 + 64 + tx * 4] = o1;
    }
}

// ---------------------------------------------------------------------------
// Persistent LSTM: 128 CTAs x 256 threads.
// CTA cb owns hidden units u0..u0+3 (16 Wh columns) for all 8 batches;
// Wh slice lives in registers. Grid barrier = per-CTA flag array + poll
// (grid.sync pattern): parallel arrivals instead of serialized atomics.
// Reduction = 31-shfl butterfly multi-reduce (32 values across 32 lanes).
// ---------------------------------------------------------------------------
__global__ void __launch_bounds__(256, 1) lstm_kernel(
    const float* __restrict__ xz, const float* __restrict__ Wh,
    float* __restrict__ h_out)
{
    const int cb = blockIdx.x;
    const int u0 = cb * 4;
    const int tid = threadIdx.x;
    const int uu = tid >> 6;      // 0..3 (unit within CTA)
    const int ks = tid & 63;      // 0..63 (k-chunk)
    const int k0 = ks * 8;
    const int lane = tid & 31;
    const int half = (tid >> 5) & 1;

    // W[g][kk] = Wh[k0+kk][g*512 + u0+uu]
    float W[4][8];
#pragma unroll
    for (int g = 0; g < 4; g++)
#pragma unroll
        for (int kk = 0; kk < 8; kk++)
            W[g][kk] = Wh[(size_t)(k0 + kk) * 2048 + g * 512 + u0 + uu];

    __shared__ float h_s[B_SZ * H_SZ];     // 16 KB
    __shared__ float red_s[4][2][32];      // [uu][half][v], v = b*4+g

    const bool owner = (tid < 32);
    const int ob = tid >> 2;   // owner batch
    const int ou = tid & 3;    // owner unit
    float c_reg = 0.f;

    for (int t = 0; t < T_SZ; t++) {
        // prefetch xz for owner threads
        float xzr0 = 0.f, xzr1 = 0.f, xzr2 = 0.f, xzr3 = 0.f;
        if (owner) {
            const float* p = xz + ((size_t)(ob * T_SZ + t)) * 2048 + u0 + ou;
            xzr0 = p[0];
            xzr1 = p[512];
            xzr2 = p[1024];
            xzr3 = p[1536];
        }

        if (t > 0) {
            // load h_{t-1} (all batches) into smem, vectorized
            {
                const float4* src = (const float4*)h_out;
                float4* dst = (float4*)h_s;
#pragma unroll
                for (int j = 0; j < 4; j++) {
                    int i4 = tid + j * 256;           // 0..1023
                    int b = i4 >> 7, kk4 = i4 & 127;
                    dst[i4] = src[((size_t)b * T_SZ + (t - 1)) * 128 + kk4];
                }
            }
            __syncthreads();

            float A[32];
#pragma unroll
            for (int v = 0; v < 32; v++) A[v] = 0.f;

#pragma unroll
            for (int b = 0; b < 8; b++) {
                const float4* hp4 = (const float4*)(h_s + b * 512 + k0);
                float4 h0 = hp4[0], h1 = hp4[1];
                float hv[8] = {h0.x, h0.y, h0.z, h0.w, h1.x, h1.y, h1.z, h1.w};
#pragma unroll
                for (int g = 0; g < 4; g++)
#pragma unroll
                    for (int kk = 0; kk < 8; kk++)
                        A[b * 4 + g] += hv[kk] * W[g][kk];
            }

            // Butterfly multi-reduce: 32 values across 32 lanes, 31 shfls.
            // After this, A[0] on lane L == sum over lanes of original A[L].
#pragma unroll
            for (int o = 16; o >= 1; o >>= 1) {
                const bool hi = (lane & o) != 0;
#pragma unroll
                for (int v = 0; v < 16; v++) {
                    if (v < o) {
                        float lo_v = A[v], hi_v = A[v + o];
                        float send = hi ? lo_v : hi_v;
                        float recv = __shfl_xor_sync(0xffffffffu, send, o);
                        A[v] = (hi ? hi_v : lo_v) + recv;
                    }
                }
            }
            red_s[uu][half][lane] = A[0];
            __syncthreads();
        }

        if (owner) {
            float zi = xzr0, zf = xzr1, zg = xzr2, zo = xzr3;
            if (t > 0) {
                int vb = ob * 4;
                zi += red_s[ou][0][vb + 0] + red_s[ou][1][vb + 0];
                zf += red_s[ou][0][vb + 1] + red_s[ou][1][vb + 1];
                zg += red_s[ou][0][vb + 2] + red_s[ou][1][vb + 2];
                zo += red_s[ou][0][vb + 3] + red_s[ou][1][vb + 3];
            }
            float ig = sigmoidf_(zi);
            float fg = sigmoidf_(zf);
            float gg = tanhf(zg);
            float og = sigmoidf_(zo);
            c_reg = fg * c_reg + ig * gg;
            float hval = og * tanhf(c_reg);
            h_out[((size_t)ob * T_SZ + t) * H_SZ + u0 + ou] = hval;
        }

        if (t < T_SZ - 1) {
            // grid barrier: release own flag, poll all 128 (warp 0), acquire.
            __syncthreads();   // h stores of this CTA happen-before the release
            if (tid == 0) {
                asm volatile("st.release.gpu.global.u32 [%0], %1;"
                             :: "l"(&g_flags[cb]), "r"((unsigned)(t + 1))
                             : "memory");
            }
            if (tid < 32) {
                const unsigned target = (unsigned)(t + 1);
                const unsigned* fp = g_flags + lane * 4;
                for (;;) {
                    unsigned f0, f1, f2, f3;
                    asm volatile("ld.volatile.global.v4.u32 {%0,%1,%2,%3}, [%4];"
                                 : "=r"(f0), "=r"(f1), "=r"(f2), "=r"(f3)
                                 : "l"(fp));
                    bool ok = (f0 >= target) & (f1 >= target) &
                              (f2 >= target) & (f3 >= target);
                    if (__all_sync(0xffffffffu, ok)) break;
                }
                asm volatile("fence.acq_rel.gpu;" ::: "memory");
            }
            __syncthreads();   // publish acquire to whole CTA
        }
    }
}

__global__ void reset_kernel() {
    if (threadIdx.x < 128) g_flags[threadIdx.x] = 0u;
}

// ---------------------------------------------------------------------------
// memory row inverse-norms and column sums
// ---------------------------------------------------------------------------
__global__ void rownorm_kernel(const float* __restrict__ mem) {
    int t = blockIdx.x;
    float4 v = ((const float4*)(mem + (size_t)t * M_SZ))[threadIdx.x];
    float ss = v.x * v.x + v.y * v.y + v.z * v.z + v.w * v.w;
    ss = blockReduceSum(ss);
    if (threadIdx.x == 0) g_invn[t] = rsqrtf(fmaxf(ss, 1e-12f));
}

__global__ void colsum_kernel(const float* __restrict__ mem) {
    int j = blockIdx.x * 256 + threadIdx.x;
    float s = 0.f;
    for (int i = 0; i < M_SZ; i++) s += mem[(size_t)i * M_SZ + j];
    g_colsum[j] = s;
}

// ---------------------------------------------------------------------------
// sim[row] = -(sum_m e_m * mem[t,m]) * invn[t] / sqrt(sum_m e_m^2)
// where e = exp(logits - max). (softmax denominator cancels in l2norm dot.)
// ---------------------------------------------------------------------------
__global__ void sim_kernel(const float* __restrict__ logits,
                           const float* __restrict__ mem,
                           float* __restrict__ simout)
{
    int row = blockIdx.x;
    int t = row & (T_SZ - 1);
    float4 xv = ((const float4*)(logits + (size_t)row * M_SZ))[threadIdx.x];
    float m = fmaxf(fmaxf(xv.x, xv.y), fmaxf(xv.z, xv.w));
    m = blockReduceMax(m);
    float e0 = __expf(xv.x - m), e1 = __expf(xv.y - m);
    float e2 = __expf(xv.z - m), e3 = __expf(xv.w - m);
    float4 mv = ((const float4*)(mem + (size_t)t * M_SZ))[threadIdx.x];
    float se2 = e0 * e0 + e1 * e1 + e2 * e2 + e3 * e3;
    float sd  = e0 * mv.x + e1 * mv.y + e2 * mv.z + e3 * mv.w;
    se2 = blockReduceSum(se2);
    sd  = blockReduceSum(sd);
    if (threadIdx.x == 0)
        simout[row] = -sd * g_invn[t] * rsqrtf(fmaxf(se2, 1e-12f));
}

// ---------------------------------------------------------------------------
// row softmax over 1024 entries; optional elementwise scale (colsum) on output
// ---------------------------------------------------------------------------
__global__ void softmax_row_kernel(const float* __restrict__ in,
                                   const float* __restrict__ scale,
                                   float* __restrict__ out)
{
    int r = blockIdx.x;
    float4 xv = ((const float4*)(in + (size_t)r * 1024))[threadIdx.x];
    float m = fmaxf(fmaxf(xv.x, xv.y), fmaxf(xv.z, xv.w));
    m = blockReduceMax(m);
    float e0 = __expf(xv.x - m), e1 = __expf(xv.y - m);
    float e2 = __expf(xv.z - m), e3 = __expf(xv.w - m);
    float S = blockReduceSum(e0 + e1 + e2 + e3);
    float inv = 1.f / S;
    float4 o = make_float4(e0 * inv, e1 * inv, e2 * inv, e3 * inv);
    if (scale) {
        float4 cs = ((const float4*)scale)[threadIdx.x];
        o.x *= cs.x; o.y *= cs.y; o.z *= cs.z; o.w *= cs.w;
    }
    ((float4*)(out + (size_t)r * 1024))[threadIdx.x] = o;
}

// ---------------------------------------------------------------------------
// new_memory[b,i,j] = (1 - ww[b,j]*sigmoid(e[b,i,j]))*mem[i,j] + ww[b,j]*a[b,i,j]
// ---------------------------------------------------------------------------
__global__ void memupd_kernel(const float* __restrict__ eb,
                              const float* __restrict__ ab,
                              const float* __restrict__ mem,
                              float* __restrict__ out)
{
    size_t idx = (size_t)blockIdx.x * blockDim.x + threadIdx.x; // over B*M*M/4
    size_t flat = idx * 4;
    int b   = (int)(flat >> 20);
    int rem = (int)(flat & 0xFFFFFu);
    int i = rem >> 10;
    int j = rem & 1023;
    float4 e = ((const float4*)eb)[idx];
    float4 a = ((const float4*)ab)[idx];
    float4 m = *(const float4*)(mem + (size_t)i * M_SZ + j);
    float4 w = *(const float4*)(g_ww + b * 1024 + j);
    float4 o;
    o.x = (1.f - w.x * sigmoidf_(e.x)) * m.x + w.x * a.x;
    o.y = (1.f - w.y * sigmoidf_(e.y)) * m.y + w.y * a.y;
    o.z = (1.f - w.z * sigmoidf_(e.z)) * m.z + w.z * a.z;
    o.w = (1.f - w.w * sigmoidf_(e.w)) * m.w + w.w * a.w;
    ((float4*)out)[idx] = o;
}

// ---------------------------------------------------------------------------
// Launch
// ---------------------------------------------------------------------------
extern "C" void kernel_launch(void* const* d_in, const int* in_sizes, int n_in,
                              void* d_out, int out_size)
{
    (void)in_sizes; (void)n_in; (void)out_size;
    const float* inputs = (const float*)d_in[0];
    const float* memory = (const float*)d_in[1];
    const float* Wx     = (const float*)d_in[2];
    const float* Wh     = (const float*)d_in[3];
    const float* bvec   = (const float*)d_in[4];
    const float* rk_W   = (const float*)d_in[5];
    const float* rk_b   = (const float*)d_in[6];
    const float* wk_W   = (const float*)d_in[7];
    const float* wk_b   = (const float*)d_in[8];
    const float* we_W   = (const float*)d_in[9];
    const float* we_b   = (const float*)d_in[10];
    const float* wa_W   = (const float*)d_in[11];
    const float* wa_b   = (const float*)d_in[12];
    float* out = (float*)d_out;

    float *xz, *h, *rk, *wk, *eb, *ab, *sim, *simw, *ww, *colsum;
    cudaGetSymbolAddress((void**)&xz,   g_xz);
    cudaGetSymbolAddress((void**)&h,    g_h);
    cudaGetSymbolAddress((void**)&rk,   g_rk);
    cudaGetSymbolAddress((void**)&wk,   g_wk);
    cudaGetSymbolAddress((void**)&eb,   g_eb);
    cudaGetSymbolAddress((void**)&ab,   g_ab);
    cudaGetSymbolAddress((void**)&sim,  g_sim);
    cudaGetSymbolAddress((void**)&simw, g_simw);
    cudaGetSymbolAddress((void**)&ww,   g_ww);
    cudaGetSymbolAddress((void**)&colsum, g_colsum);

    const int MROWS = B_SZ * T_SZ; // 8192

    reset_kernel<<<1, 128>>>();
    rownorm_kernel<<<M_SZ, 256>>>(memory);
    colsum_kernel<<<M_SZ / 256, 256>>>(memory);

    // xz = inputs @ Wx + b       (8192 x 2048, K=256)
    sgemm_kernel<<<dim3(2048 / 128, MROWS / 128, 1), 256>>>(
        inputs, Wx, bvec, xz, MROWS, 2048, 256, 0, 0, 0);

    // LSTM scan -> h
    lstm_kernel<<<128, 256>>>(xz, Wh, h);

    // rk logits (4 heads):  h @ rk_W[r] + rk_b[r]   (8192 x 1024, K=512)
    sgemm_kernel<<<dim3(1024 / 128, MROWS / 128, R_SZ), 256>>>(
        h, rk_W, rk_b, rk, MROWS, 1024, 512,
        (long)H_SZ * M_SZ, (long)M_SZ, (long)MROWS * M_SZ);
    sim_kernel<<<R_SZ * B_SZ * T_SZ, 256>>>(rk, memory, sim);

    // wk logits: h @ wk_W + wk_b
    sgemm_kernel<<<dim3(1024 / 128, MROWS / 128, 1), 256>>>(
        h, wk_W, wk_b, wk, MROWS, 1024, 512, 0, 0, 0);
    sim_kernel<<<B_SZ * T_SZ, 256>>>(wk, memory, simw);

    // reads[r,b,:] = softmax_t(sim) * colsum   -> out[0 : 32768)
    softmax_row_kernel<<<R_SZ * B_SZ, 256>>>(sim, colsum, out);
    // ww[b,:] = softmax_t(simw)
    softmax_row_kernel<<<B_SZ, 256>>>(simw, (const float*)nullptr, ww);

    // erase / add logits
    sgemm_kernel<<<dim3(1024 / 128, MROWS / 128, 1), 256>>>(
        h, we_W, we_b, eb, MROWS, 1024, 512, 0, 0, 0);
    sgemm_kernel<<<dim3(1024 / 128, MROWS / 128, 1), 256>>>(
        h, wa_W, wa_b, ab, MROWS, 1024, 512, 0, 0, 0);

    // new_memory -> out[32768 : 32768 + 8M)
    memupd_kernel<<<(B_SZ * M_SZ * M_SZ / 4) / 256, 256>>>(
        eb, ab, memory, out + R_SZ * B_SZ * T_SZ);
}

// round 5
// speedup vs baseline: 2.2534x; 2.2534x over previous
#include <cuda_runtime.h>
#include <cstdint>
#include <cstddef>

#define B_SZ 8
#define T_SZ 1024
#define D_SZ 256
#define H_SZ 512
#define M_SZ 1024
#define R_SZ 4

// ---------------------------------------------------------------------------
// Scratch (static device globals -- no runtime allocation allowed)
// ---------------------------------------------------------------------------
__device__ float g_xz[(size_t)B_SZ * T_SZ * 4 * H_SZ];   // 64 MB  [b*T+t][4H]
__device__ float g_h [(size_t)B_SZ * T_SZ * H_SZ];       // 16 MB  [b*T+t][H]
__device__ float g_rk[(size_t)R_SZ * B_SZ * T_SZ * M_SZ];// 128 MB [r][b*T+t][M]
__device__ float g_wk[(size_t)B_SZ * T_SZ * M_SZ];       // 32 MB
__device__ float g_eb[(size_t)B_SZ * T_SZ * M_SZ];       // 32 MB erase logits
__device__ float g_ab[(size_t)B_SZ * T_SZ * M_SZ];       // 32 MB add logits
__device__ float g_sim [R_SZ * B_SZ * T_SZ];
__device__ float g_simw[B_SZ * T_SZ];
__device__ float g_ww  [B_SZ * T_SZ];
__device__ float g_invn[M_SZ];
__device__ float g_colsum[M_SZ];
__device__ unsigned g_bar;          // single grid-barrier counter (reset per launch)

// ---------------------------------------------------------------------------
// Block-wide reductions (blockDim.x == 256)
// ---------------------------------------------------------------------------
__device__ __forceinline__ float blockReduceSum(float v) {
    __shared__ float sh[8];
    int lane = threadIdx.x & 31, w = threadIdx.x >> 5;
#pragma unroll
    for (int o = 16; o; o >>= 1) v += __shfl_xor_sync(0xffffffffu, v, o);
    if (lane == 0) sh[w] = v;
    __syncthreads();
    if (w == 0) {
        float x = (lane < 8) ? sh[lane] : 0.f;
#pragma unroll
        for (int o = 4; o; o >>= 1) x += __shfl_xor_sync(0xffffffffu, x, o);
        if (lane == 0) sh[0] = x;
    }
    __syncthreads();
    float r = sh[0];
    __syncthreads();
    return r;
}

__device__ __forceinline__ float blockReduceMax(float v) {
    __shared__ float sh[8];
    int lane = threadIdx.x & 31, w = threadIdx.x >> 5;
#pragma unroll
    for (int o = 16; o; o >>= 1) v = fmaxf(v, __shfl_xor_sync(0xffffffffu, v, o));
    if (lane == 0) sh[w] = v;
    __syncthreads();
    if (w == 0) {
        float x = (lane < 8) ? sh[lane] : -3.402823466e38f;
#pragma unroll
        for (int o = 4; o; o >>= 1) x = fmaxf(x, __shfl_xor_sync(0xffffffffu, x, o));
        if (lane == 0) sh[0] = x;
    }
    __syncthreads();
    float r = sh[0];
    __syncthreads();
    return r;
}

__device__ __forceinline__ float sigmoidf_(float x) {
    return 1.f / (1.f + __expf(-x));
}

// ---------------------------------------------------------------------------
// Generic SGEMM: C = A[M,K] @ B[K,N] + bias[N]   (128x128 tile, 256 threads)
// ---------------------------------------------------------------------------
__global__ void __launch_bounds__(256) sgemm_kernel(
    const float* __restrict__ A, const float* __restrict__ B,
    const float* __restrict__ bias, float* __restrict__ C,
    int M, int N, int K, long zB, long zBias, long zC)
{
    const int n0 = blockIdx.x * 128;
    const int m0 = blockIdx.y * 128;
    B    += (size_t)blockIdx.z * (size_t)zB;
    bias += (size_t)blockIdx.z * (size_t)zBias;
    C    += (size_t)blockIdx.z * (size_t)zC;

    __shared__ float As[8][128];
    __shared__ float Bs[8][128];

    const int tid  = threadIdx.x;
    const int arow = tid >> 1, ak = (tid & 1) * 4;
    const int bk   = tid >> 5, bc = (tid & 31) * 4;
    const int tx   = tid & 15, ty = tid >> 4;

    const float* Ap = A + (size_t)(m0 + arow) * K + ak;
    const float* Bp = B + (size_t)bk * N + n0 + bc;

    float4 aR = *(const float4*)Ap;
    float4 bR = *(const float4*)Bp;

    float acc[8][8];
#pragma unroll
    for (int i = 0; i < 8; i++)
#pragma unroll
        for (int j = 0; j < 8; j++) acc[i][j] = 0.f;

    const int KT = K >> 3;
    for (int kt = 0; kt < KT; kt++) {
        As[ak + 0][arow] = aR.x;
        As[ak + 1][arow] = aR.y;
        As[ak + 2][arow] = aR.z;
        As[ak + 3][arow] = aR.w;
        *(float4*)&Bs[bk][bc] = bR;
        __syncthreads();
        if (kt + 1 < KT) {
            aR = *(const float4*)(Ap + (kt + 1) * 8);
            bR = *(const float4*)(Bp + (size_t)(kt + 1) * 8 * N);
        }
#pragma unroll
        for (int kk = 0; kk < 8; kk++) {
            float4 a0 = *(const float4*)&As[kk][ty * 4];
            float4 a1 = *(const float4*)&As[kk][64 + ty * 4];
            float4 b0 = *(const float4*)&Bs[kk][tx * 4];
            float4 b1 = *(const float4*)&Bs[kk][64 + tx * 4];
            float ar[8] = {a0.x, a0.y, a0.z, a0.w, a1.x, a1.y, a1.z, a1.w};
            float br[8] = {b0.x, b0.y, b0.z, b0.w, b1.x, b1.y, b1.z, b1.w};
#pragma unroll
            for (int i = 0; i < 8; i++)
#pragma unroll
                for (int j = 0; j < 8; j++) acc[i][j] += ar[i] * br[j];
        }
        __syncthreads();
    }

    float4 bias0 = *(const float4*)&bias[n0 + tx * 4];
    float4 bias1 = *(const float4*)&bias[n0 + 64 + tx * 4];
    float bb[8] = {bias0.x, bias0.y, bias0.z, bias0.w,
                   bias1.x, bias1.y, bias1.z, bias1.w};
#pragma unroll
    for (int i = 0; i < 8; i++) {
        int row = m0 + ((i < 4) ? (ty * 4 + i) : (64 + ty * 4 + (i - 4)));
        float4 o0 = make_float4(acc[i][0] + bb[0], acc[i][1] + bb[1],
                                acc[i][2] + bb[2], acc[i][3] + bb[3]);
        float4 o1 = make_float4(acc[i][4] + bb[4], acc[i][5] + bb[5],
                                acc[i][6] + bb[6], acc[i][7] + bb[7]);
        *(float4*)&C[(size_t)row * N + n0 + tx * 4]      = o0;
        *(float4*)&C[(size_t)row * N + n0 + 64 + tx * 4] = o1;
    }
}

// ---------------------------------------------------------------------------
// Persistent LSTM: 128 CTAs x 256 threads.
// CTA cb owns hidden units u0..u0+3 (16 Wh columns) for all 8 batches;
// Wh slice lives in registers.
// Grid barrier = single counter, CG grid.sync pattern:
//   tid0: red.release.gpu.add  then  ld.acquire.gpu spin  (one reader/CTA).
// Reduction = 31-shfl butterfly multi-reduce (proven bit-identical in R4).
// ---------------------------------------------------------------------------
__global__ void __launch_bounds__(256, 1) lstm_kernel(
    const float* __restrict__ xz, const float* __restrict__ Wh,
    float* __restrict__ h_out)
{
    const int cb = blockIdx.x;
    const int u0 = cb * 4;
    const int tid = threadIdx.x;
    const int uu = tid >> 6;      // 0..3 (unit within CTA)
    const int ks = tid & 63;      // 0..63 (k-chunk)
    const int k0 = ks * 8;
    const int lane = tid & 31;
    const int half = (tid >> 5) & 1;

    // W[g][kk] = Wh[k0+kk][g*512 + u0+uu]
    float W[4][8];
#pragma unroll
    for (int g = 0; g < 4; g++)
#pragma unroll
        for (int kk = 0; kk < 8; kk++)
            W[g][kk] = Wh[(size_t)(k0 + kk) * 2048 + g * 512 + u0 + uu];

    __shared__ float h_s[B_SZ * H_SZ];     // 16 KB
    __shared__ float red_s[4][2][32];      // [uu][half][v], v = b*4+g

    const bool owner = (tid < 32);
    const int ob = tid >> 2;   // owner batch
    const int ou = tid & 3;    // owner unit
    float c_reg = 0.f;

    for (int t = 0; t < T_SZ; t++) {
        // prefetch xz for owner threads
        float xzr0 = 0.f, xzr1 = 0.f, xzr2 = 0.f, xzr3 = 0.f;
        if (owner) {
            const float* p = xz + ((size_t)(ob * T_SZ + t)) * 2048 + u0 + ou;
            xzr0 = p[0];
            xzr1 = p[512];
            xzr2 = p[1024];
            xzr3 = p[1536];
        }

        if (t > 0) {
            // load h_{t-1} (all batches) into smem, vectorized
            {
                const float4* src = (const float4*)h_out;
                float4* dst = (float4*)h_s;
#pragma unroll
                for (int j = 0; j < 4; j++) {
                    int i4 = tid + j * 256;           // 0..1023
                    int b = i4 >> 7, kk4 = i4 & 127;
                    dst[i4] = src[((size_t)b * T_SZ + (t - 1)) * 128 + kk4];
                }
            }
            __syncthreads();

            float A[32];
#pragma unroll
            for (int v = 0; v < 32; v++) A[v] = 0.f;

#pragma unroll
            for (int b = 0; b < 8; b++) {
                const float4* hp4 = (const float4*)(h_s + b * 512 + k0);
                float4 h0 = hp4[0], h1 = hp4[1];
                float hv[8] = {h0.x, h0.y, h0.z, h0.w, h1.x, h1.y, h1.z, h1.w};
#pragma unroll
                for (int g = 0; g < 4; g++)
#pragma unroll
                    for (int kk = 0; kk < 8; kk++)
                        A[b * 4 + g] += hv[kk] * W[g][kk];
            }

            // Butterfly multi-reduce: 32 values across 32 lanes, 31 shfls.
            // After this, A[0] on lane L == sum over lanes of original A[L].
#pragma unroll
            for (int o = 16; o >= 1; o >>= 1) {
                const bool hi = (lane & o) != 0;
#pragma unroll
                for (int v = 0; v < 16; v++) {
                    if (v < o) {
                        float lo_v = A[v], hi_v = A[v + o];
                        float send = hi ? lo_v : hi_v;
                        float recv = __shfl_xor_sync(0xffffffffu, send, o);
                        A[v] = (hi ? hi_v : lo_v) + recv;
                    }
                }
            }
            red_s[uu][half][lane] = A[0];
            __syncthreads();
        }

        if (owner) {
            float zi = xzr0, zf = xzr1, zg = xzr2, zo = xzr3;
            if (t > 0) {
                int vb = ob * 4;
                zi += red_s[ou][0][vb + 0] + red_s[ou][1][vb + 0];
                zf += red_s[ou][0][vb + 1] + red_s[ou][1][vb + 1];
                zg += red_s[ou][0][vb + 2] + red_s[ou][1][vb + 2];
                zo += red_s[ou][0][vb + 3] + red_s[ou][1][vb + 3];
            }
            float ig = sigmoidf_(zi);
            float fg = sigmoidf_(zf);
            float gg = tanhf(zg);
            float og = sigmoidf_(zo);
            c_reg = fg * c_reg + ig * gg;
            float hval = og * tanhf(c_reg);
            h_out[((size_t)ob * T_SZ + t) * H_SZ + u0 + ou] = hval;
        }

        if (t < T_SZ - 1) {
            // Grid barrier (CG grid.sync pattern).
            // bar.sync orders this CTA's h stores before tid0's release-RED;
            // acquire-load + bar.sync publishes everyone's h to all threads.
            __syncthreads();
            if (tid == 0) {
                asm volatile("red.release.gpu.global.add.u32 [%0], %1;"
                             :: "l"(&g_bar), "r"(1u) : "memory");
                const unsigned target = (unsigned)(t + 1) * 128u;
                unsigned v;
                do {
                    asm volatile("ld.acquire.gpu.global.u32 %0, [%1];"
                                 : "=r"(v) : "l"(&g_bar) : "memory");
                } while (v < target);
            }
            __syncthreads();
        }
    }
}

__global__ void reset_kernel() {
    if (threadIdx.x == 0) g_bar = 0u;
}

// ---------------------------------------------------------------------------
// memory row inverse-norms and column sums
// ---------------------------------------------------------------------------
__global__ void rownorm_kernel(const float* __restrict__ mem) {
    int t = blockIdx.x;
    float4 v = ((const float4*)(mem + (size_t)t * M_SZ))[threadIdx.x];
    float ss = v.x * v.x + v.y * v.y + v.z * v.z + v.w * v.w;
    ss = blockReduceSum(ss);
    if (threadIdx.x == 0) g_invn[t] = rsqrtf(fmaxf(ss, 1e-12f));
}

__global__ void colsum_kernel(const float* __restrict__ mem) {
    int j = blockIdx.x * 256 + threadIdx.x;
    float s = 0.f;
    for (int i = 0; i < M_SZ; i++) s += mem[(size_t)i * M_SZ + j];
    g_colsum[j] = s;
}

// ---------------------------------------------------------------------------
// sim[row] = -(sum_m e_m * mem[t,m]) * invn[t] / sqrt(sum_m e_m^2)
// where e = exp(logits - max). (softmax denominator cancels in l2norm dot.)
// ---------------------------------------------------------------------------
__global__ void sim_kernel(const float* __restrict__ logits,
                           const float* __restrict__ mem,
                           float* __restrict__ simout)
{
    int row = blockIdx.x;
    int t = row & (T_SZ - 1);
    float4 xv = ((const float4*)(logits + (size_t)row * M_SZ))[threadIdx.x];
    float m = fmaxf(fmaxf(xv.x, xv.y), fmaxf(xv.z, xv.w));
    m = blockReduceMax(m);
    float e0 = __expf(xv.x - m), e1 = __expf(xv.y - m);
    float e2 = __expf(xv.z - m), e3 = __expf(xv.w - m);
    float4 mv = ((const float4*)(mem + (size_t)t * M_SZ))[threadIdx.x];
    float se2 = e0 * e0 + e1 * e1 + e2 * e2 + e3 * e3;
    float sd  = e0 * mv.x + e1 * mv.y + e2 * mv.z + e3 * mv.w;
    se2 = blockReduceSum(se2);
    sd  = blockReduceSum(sd);
    if (threadIdx.x == 0)
        simout[row] = -sd * g_invn[t] * rsqrtf(fmaxf(se2, 1e-12f));
}

// ---------------------------------------------------------------------------
// row softmax over 1024 entries; optional elementwise scale (colsum) on output
// ---------------------------------------------------------------------------
__global__ void softmax_row_kernel(const float* __restrict__ in,
                                   const float* __restrict__ scale,
                                   float* __restrict__ out)
{
    int r = blockIdx.x;
    float4 xv = ((const float4*)(in + (size_t)r * 1024))[threadIdx.x];
    float m = fmaxf(fmaxf(xv.x, xv.y), fmaxf(xv.z, xv.w));
    m = blockReduceMax(m);
    float e0 = __expf(xv.x - m), e1 = __expf(xv.y - m);
    float e2 = __expf(xv.z - m), e3 = __expf(xv.w - m);
    float S = blockReduceSum(e0 + e1 + e2 + e3);
    float inv = 1.f / S;
    float4 o = make_float4(e0 * inv, e1 * inv, e2 * inv, e3 * inv);
    if (scale) {
        float4 cs = ((const float4*)scale)[threadIdx.x];
        o.x *= cs.x; o.y *= cs.y; o.z *= cs.z; o.w *= cs.w;
    }
    ((float4*)(out + (size_t)r * 1024))[threadIdx.x] = o;
}

// ---------------------------------------------------------------------------
// new_memory[b,i,j] = (1 - ww[b,j]*sigmoid(e[b,i,j]))*mem[i,j] + ww[b,j]*a[b,i,j]
// ---------------------------------------------------------------------------
__global__ void memupd_kernel(const float* __restrict__ eb,
                              const float* __restrict__ ab,
                              const float* __restrict__ mem,
                              float* __restrict__ out)
{
    size_t idx = (size_t)blockIdx.x * blockDim.x + threadIdx.x; // over B*M*M/4
    size_t flat = idx * 4;
    int b   = (int)(flat >> 20);
    int rem = (int)(flat & 0xFFFFFu);
    int i = rem >> 10;
    int j = rem & 1023;
    float4 e = ((const float4*)eb)[idx];
    float4 a = ((const float4*)ab)[idx];
    float4 m = *(const float4*)(mem + (size_t)i * M_SZ + j);
    float4 w = *(const float4*)(g_ww + b * 1024 + j);
    float4 o;
    o.x = (1.f - w.x * sigmoidf_(e.x)) * m.x + w.x * a.x;
    o.y = (1.f - w.y * sigmoidf_(e.y)) * m.y + w.y * a.y;
    o.z = (1.f - w.z * sigmoidf_(e.z)) * m.z + w.z * a.z;
    o.w = (1.f - w.w * sigmoidf_(e.w)) * m.w + w.w * a.w;
    ((float4*)out)[idx] = o;
}

// ---------------------------------------------------------------------------
// Launch
// ---------------------------------------------------------------------------
extern "C" void kernel_launch(void* const* d_in, const int* in_sizes, int n_in,
                              void* d_out, int out_size)
{
    (void)in_sizes; (void)n_in; (void)out_size;
    const float* inputs = (const float*)d_in[0];
    const float* memory = (const float*)d_in[1];
    const float* Wx     = (const float*)d_in[2];
    const float* Wh     = (const float*)d_in[3];
    const float* bvec   = (const float*)d_in[4];
    const float* rk_W   = (const float*)d_in[5];
    const float* rk_b   = (const float*)d_in[6];
    const float* wk_W   = (const float*)d_in[7];
    const float* wk_b   = (const float*)d_in[8];
    const float* we_W   = (const float*)d_in[9];
    const float* we_b   = (const float*)d_in[10];
    const float* wa_W   = (const float*)d_in[11];
    const float* wa_b   = (const float*)d_in[12];
    float* out = (float*)d_out;

    float *xz, *h, *rk, *wk, *eb, *ab, *sim, *simw, *ww, *colsum;
    cudaGetSymbolAddress((void**)&xz,   g_xz);
    cudaGetSymbolAddress((void**)&h,    g_h);
    cudaGetSymbolAddress((void**)&rk,   g_rk);
    cudaGetSymbolAddress((void**)&wk,   g_wk);
    cudaGetSymbolAddress((void**)&eb,   g_eb);
    cudaGetSymbolAddress((void**)&ab,   g_ab);
    cudaGetSymbolAddress((void**)&sim,  g_sim);
    cudaGetSymbolAddress((void**)&simw, g_simw);
    cudaGetSymbolAddress((void**)&ww,   g_ww);
    cudaGetSymbolAddress((void**)&colsum, g_colsum);

    const int MROWS = B_SZ * T_SZ; // 8192

    reset_kernel<<<1, 32>>>();
    rownorm_kernel<<<M_SZ, 256>>>(memory);
    colsum_kernel<<<M_SZ / 256, 256>>>(memory);

    // xz = inputs @ Wx + b       (8192 x 2048, K=256)
    sgemm_kernel<<<dim3(2048 / 128, MROWS / 128, 1), 256>>>(
        inputs, Wx, bvec, xz, MROWS, 2048, 256, 0, 0, 0);

    // LSTM scan -> h
    lstm_kernel<<<128, 256>>>(xz, Wh, h);

    // rk logits (4 heads):  h @ rk_W[r] + rk_b[r]   (8192 x 1024, K=512)
    sgemm_kernel<<<dim3(1024 / 128, MROWS / 128, R_SZ), 256>>>(
        h, rk_W, rk_b, rk, MROWS, 1024, 512,
        (long)H_SZ * M_SZ, (long)M_SZ, (long)MROWS * M_SZ);
    sim_kernel<<<R_SZ * B_SZ * T_SZ, 256>>>(rk, memory, sim);

    // wk logits: h @ wk_W + wk_b
    sgemm_kernel<<<dim3(1024 / 128, MROWS / 128, 1), 256>>>(
        h, wk_W, wk_b, wk, MROWS, 1024, 512, 0, 0, 0);
    sim_kernel<<<B_SZ * T_SZ, 256>>>(wk, memory, simw);

    // reads[r,b,:] = softmax_t(sim) * colsum   -> out[0 : 32768)
    softmax_row_kernel<<<R_SZ * B_SZ, 256>>>(sim, colsum, out);
    // ww[b,:] = softmax_t(simw)
    softmax_row_kernel<<<B_SZ, 256>>>(simw, (const float*)nullptr, ww);

    // erase / add logits
    sgemm_kernel<<<dim3(1024 / 128, MROWS / 128, 1), 256>>>(
        h, we_W, we_b, eb, MROWS, 1024, 512, 0, 0, 0);
    sgemm_kernel<<<dim3(1024 / 128, MROWS / 128, 1), 256>>>(
        h, wa_W, wa_b, ab, MROWS, 1024, 512, 0, 0, 0);

    // new_memory -> out[32768 : 32768 + 8M)
    memupd_kernel<<<(B_SZ * M_SZ * M_SZ / 4) / 256, 256>>>(
        eb, ab, memory, out + R_SZ * B_SZ * T_SZ);
}